// round 1
// baseline (speedup 1.0000x reference)
#include <cuda_runtime.h>

#define N_NODES 50000
#define N_EDGES 800000
#define D_IN    256
#define D_OUT   64
#define NEG_SLOPE 0.2f

// Scratch for the dense projection: support = x @ W^T + b   [N_NODES, D_OUT]
__device__ float g_support[N_NODES * D_OUT];

// ---------------------------------------------------------------------------
// Kernel 1: zero d_out (it is poisoned to 0xAA before timing)
// ---------------------------------------------------------------------------
__global__ void zero_kernel(float4* __restrict__ out, int n4) {
    int i = blockIdx.x * blockDim.x + threadIdx.x;
    if (i < n4) out[i] = make_float4(0.f, 0.f, 0.f, 0.f);
}

// ---------------------------------------------------------------------------
// Kernel 2: support = x @ W^T + b
//   x [N,256] row-major, W [64,256] row-major, support [N,64]
//   256 threads/block, 64 nodes per block, K-tiles of 64, 4x4 register tile.
// ---------------------------------------------------------------------------
__global__ __launch_bounds__(256) void gemm_kernel(
    const float* __restrict__ x,
    const float* __restrict__ W,
    const float* __restrict__ b,
    float* __restrict__ support)
{
    __shared__ float xs[64][68];  // [k][node], padded (68%4==0 keeps float4 alignment)
    __shared__ float ws[64][68];  // [k][out]

    const int tid = threadIdx.x;
    const int node_base = blockIdx.x * 64;
    const int tx = tid & 15;   // out group   (4 outs each)
    const int ty = tid >> 4;   // node group  (4 nodes each)

    float acc[4][4];
    #pragma unroll
    for (int i = 0; i < 4; i++)
        #pragma unroll
        for (int j = 0; j < 4; j++) acc[i][j] = 0.f;

    for (int kt = 0; kt < D_IN; kt += 64) {
        // --- load x tile [64 nodes][64 k] -> xs[k][node] ---
        #pragma unroll
        for (int i = 0; i < 4; i++) {
            int idx  = tid + i * 256;     // 0..1023 float4 slots
            int row  = idx >> 4;          // node within tile
            int col4 = idx & 15;          // float4 within the 64-wide k slice
            int gnode = node_base + row;
            float4 v = make_float4(0.f, 0.f, 0.f, 0.f);
            if (gnode < N_NODES)
                v = *(const float4*)&x[(size_t)gnode * D_IN + kt + col4 * 4];
            xs[col4 * 4 + 0][row] = v.x;
            xs[col4 * 4 + 1][row] = v.y;
            xs[col4 * 4 + 2][row] = v.z;
            xs[col4 * 4 + 3][row] = v.w;
        }
        // --- load W tile [64 outs][64 k] -> ws[k][out] ---
        #pragma unroll
        for (int i = 0; i < 4; i++) {
            int idx  = tid + i * 256;
            int row  = idx >> 4;          // out index
            int col4 = idx & 15;
            float4 v = *(const float4*)&W[(size_t)row * D_IN + kt + col4 * 4];
            ws[col4 * 4 + 0][row] = v.x;
            ws[col4 * 4 + 1][row] = v.y;
            ws[col4 * 4 + 2][row] = v.z;
            ws[col4 * 4 + 3][row] = v.w;
        }
        __syncthreads();

        #pragma unroll 8
        for (int k = 0; k < 64; k++) {
            float4 a = *(const float4*)&xs[k][ty * 4];   // broadcast within half-warp
            float4 w = *(const float4*)&ws[k][tx * 4];   // conflict-free
            acc[0][0] += a.x * w.x; acc[0][1] += a.x * w.y; acc[0][2] += a.x * w.z; acc[0][3] += a.x * w.w;
            acc[1][0] += a.y * w.x; acc[1][1] += a.y * w.y; acc[1][2] += a.y * w.z; acc[1][3] += a.y * w.w;
            acc[2][0] += a.z * w.x; acc[2][1] += a.z * w.y; acc[2][2] += a.z * w.z; acc[2][3] += a.z * w.w;
            acc[3][0] += a.w * w.x; acc[3][1] += a.w * w.y; acc[3][2] += a.w * w.z; acc[3][3] += a.w * w.w;
        }
        __syncthreads();
    }

    // write out (+bias)
    #pragma unroll
    for (int i = 0; i < 4; i++) {
        int gnode = node_base + ty * 4 + i;
        if (gnode >= N_NODES) break;
        int o = tx * 4;
        float4 r;
        r.x = acc[i][0] + b[o + 0];
        r.y = acc[i][1] + b[o + 1];
        r.z = acc[i][2] + b[o + 2];
        r.w = acc[i][3] + b[o + 3];
        *(float4*)&support[(size_t)gnode * D_OUT + o] = r;
    }
}

// ---------------------------------------------------------------------------
// Kernel 3: edge aggregation with register run-accumulation (edge_dst sorted)
//   out[d][c] += sum_{e: dst[e]==d} val[e] * support[src[e]][c]
//   One warp = EDGES_PER_WARP contiguous edges. Lane owns columns {lane, lane+32}.
// ---------------------------------------------------------------------------
#define EDGES_PER_WARP 128

__global__ __launch_bounds__(256) void agg_kernel(
    const int*   __restrict__ edge_src,
    const int*   __restrict__ edge_dst,
    const float* __restrict__ edge_val,
    const float* __restrict__ support,
    float*       __restrict__ out)
{
    const int warp = (blockIdx.x * blockDim.x + threadIdx.x) >> 5;
    const int lane = threadIdx.x & 31;
    const int start = warp * EDGES_PER_WARP;
    if (start >= N_EDGES) return;
    const int end = min(N_EDGES, start + EDGES_PER_WARP);

    float acc0 = 0.f, acc1 = 0.f;
    int cur = __ldg(&edge_dst[start]);

    for (int e = start; e < end; e++) {
        const int   dst = __ldg(&edge_dst[e]);   // broadcast (warp-uniform)
        if (dst != cur) {
            atomicAdd(&out[(size_t)cur * D_OUT + lane],      acc0);
            atomicAdd(&out[(size_t)cur * D_OUT + lane + 32], acc1);
            acc0 = 0.f; acc1 = 0.f;
            cur = dst;
        }
        const int   src = __ldg(&edge_src[e]);
        const float v   = __ldg(&edge_val[e]);
        const float* srow = &support[(size_t)src * D_OUT];
        acc0 += v * srow[lane];
        acc1 += v * srow[lane + 32];
    }
    atomicAdd(&out[(size_t)cur * D_OUT + lane],      acc0);
    atomicAdd(&out[(size_t)cur * D_OUT + lane + 32], acc1);
}

// ---------------------------------------------------------------------------
// Kernel 4: in-place LeakyReLU on d_out
// ---------------------------------------------------------------------------
__global__ void relu_kernel(float4* __restrict__ out, int n4) {
    int i = blockIdx.x * blockDim.x + threadIdx.x;
    if (i >= n4) return;
    float4 v = out[i];
    v.x = (v.x >= 0.f) ? v.x : NEG_SLOPE * v.x;
    v.y = (v.y >= 0.f) ? v.y : NEG_SLOPE * v.y;
    v.z = (v.z >= 0.f) ? v.z : NEG_SLOPE * v.z;
    v.w = (v.w >= 0.f) ? v.w : NEG_SLOPE * v.w;
    out[i] = v;
}

// ---------------------------------------------------------------------------
// Launch
// ---------------------------------------------------------------------------
extern "C" void kernel_launch(void* const* d_in, const int* in_sizes, int n_in,
                              void* d_out, int out_size) {
    const float* x        = (const float*)d_in[0];
    const float* W        = (const float*)d_in[1];
    const float* b        = (const float*)d_in[2];
    const int*   edge_src = (const int*)  d_in[3];
    const int*   edge_dst = (const int*)  d_in[4];
    const float* edge_val = (const float*)d_in[5];
    float* out = (float*)d_out;

    float* support;
    cudaGetSymbolAddress((void**)&support, g_support);

    const int n_out   = N_NODES * D_OUT;          // 3.2M
    const int n4      = n_out / 4;

    // 1. zero output
    zero_kernel<<<(n4 + 255) / 256, 256>>>((float4*)out, n4);

    // 2. dense projection
    gemm_kernel<<<(N_NODES + 63) / 64, 256>>>(x, W, b, support);

    // 3. sparse aggregation
    const int n_warps  = (N_EDGES + EDGES_PER_WARP - 1) / EDGES_PER_WARP;
    const int n_blocks = (n_warps * 32 + 255) / 256;
    agg_kernel<<<n_blocks, 256>>>(edge_src, edge_dst, edge_val, support, out);

    // 4. leaky relu
    relu_kernel<<<(n4 + 255) / 256, 256>>>((float4*)out, n4);
}

// round 4
// speedup vs baseline: 1.4712x; 1.4712x over previous
#include <cuda_runtime.h>
#include <cstdint>

#define N_NODES 50000
#define N_EDGES 800000
#define D_IN    256
#define D_OUT   64
#define NEG_SLOPE 0.2f

// Scratch: support = x @ W^T + b   [N_NODES, D_OUT]
__device__ float g_support[N_NODES * D_OUT];
// CSR row pointers for sorted edge_dst
__device__ int g_rowptr[N_NODES + 1];

// ---------------------------------------------------------------------------
// TF32 helpers
// ---------------------------------------------------------------------------
__device__ __forceinline__ void tf32_split(float f, uint32_t& hi, uint32_t& lo) {
    uint32_t h;
    asm("cvt.rna.tf32.f32 %0, %1;" : "=r"(h) : "f"(f));
    float hf = __uint_as_float(h);
    float lf = f - hf;
    asm("cvt.rna.tf32.f32 %0, %1;" : "=r"(lo) : "f"(lf));
    hi = h;
}

__device__ __forceinline__ void mma_tf32(float c[4], const uint32_t a[4], const uint32_t b[2]) {
    asm volatile(
        "mma.sync.aligned.m16n8k8.row.col.f32.tf32.tf32.f32 "
        "{%0,%1,%2,%3}, {%4,%5,%6,%7}, {%8,%9}, {%0,%1,%2,%3};"
        : "+f"(c[0]), "+f"(c[1]), "+f"(c[2]), "+f"(c[3])
        : "r"(a[0]), "r"(a[1]), "r"(a[2]), "r"(a[3]), "r"(b[0]), "r"(b[1]));
}

// ---------------------------------------------------------------------------
// Kernel 1: support = x @ W^T + b  via tf32 tensor cores (3xTF32 accuracy)
//   Block: 256 threads (8 warps). Each warp: 16 rows x 64 cols. Block: 128 rows.
//   Both x and W staged in K_CHUNK=32 slices. Static smem = 27.6 KB.
// ---------------------------------------------------------------------------
#define K_CHUNK 32
#define XPAD 36   // 36 mod 32 == 4 -> conflict-free; 144B row stride, 16B aligned

__global__ __launch_bounds__(256) void gemm_tf32_kernel(
    const float* __restrict__ x,
    const float* __restrict__ W,
    const float* __restrict__ bias,
    float* __restrict__ support)
{
    __shared__ float xs[128][XPAD];  // [row][k-chunk]
    __shared__ float ws[64][XPAD];   // [out][k-chunk]

    const int tid  = threadIdx.x;
    const int warp = tid >> 5;
    const int lane = tid & 31;
    const int gq   = lane >> 2;   // 0..7 (row group)
    const int tq   = lane & 3;    // 0..3 (col group)
    const int row_base = blockIdx.x * 128;

    float acc[8][4];
    #pragma unroll
    for (int nt = 0; nt < 8; nt++)
        #pragma unroll
        for (int j = 0; j < 4; j++) acc[nt][j] = 0.f;

    for (int kt = 0; kt < D_IN; kt += K_CHUNK) {
        // Stage x tile [128 rows][32 k]: 1024 float4, 4 per thread
        #pragma unroll
        for (int i = 0; i < 4; i++) {
            int idx = tid + i * 256;
            int r   = idx >> 3;        // 0..127
            int c4  = idx & 7;         // float4 slot in 32-wide chunk
            int gr  = row_base + r;
            float4 v = make_float4(0.f, 0.f, 0.f, 0.f);
            if (gr < N_NODES)
                v = *(const float4*)&x[(size_t)gr * D_IN + kt + c4 * 4];
            *(float4*)&xs[r][c4 * 4] = v;
        }
        // Stage W tile [64 outs][32 k]: 512 float4, 2 per thread
        #pragma unroll
        for (int i = 0; i < 2; i++) {
            int idx = tid + i * 256;
            int r   = idx >> 3;        // 0..63
            int c4  = idx & 7;
            *(float4*)&ws[r][c4 * 4] = *(const float4*)&W[(size_t)r * D_IN + kt + c4 * 4];
        }
        __syncthreads();

        #pragma unroll
        for (int k8 = 0; k8 < K_CHUNK; k8 += 8) {
            // A fragment (m16n8k8 row-major layout)
            const int r0 = warp * 16 + gq;
            float af[4];
            af[0] = xs[r0    ][k8 + tq];
            af[1] = xs[r0 + 8][k8 + tq];
            af[2] = xs[r0    ][k8 + tq + 4];
            af[3] = xs[r0 + 8][k8 + tq + 4];
            uint32_t ah[4], al[4];
            #pragma unroll
            for (int j = 0; j < 4; j++) tf32_split(af[j], ah[j], al[j]);

            #pragma unroll
            for (int nt = 0; nt < 8; nt++) {
                // B fragment (col-major == W row-major [n][k])
                const int n0 = nt * 8 + gq;
                float bf0 = ws[n0][k8 + tq];
                float bf1 = ws[n0][k8 + tq + 4];
                uint32_t bh[2], bl[2];
                tf32_split(bf0, bh[0], bl[0]);
                tf32_split(bf1, bh[1], bl[1]);
                mma_tf32(acc[nt], ah, bh);   // hi*hi
                mma_tf32(acc[nt], ah, bl);   // hi*lo
                mma_tf32(acc[nt], al, bh);   // lo*hi
            }
        }
        __syncthreads();
    }

    // Epilogue: C fragment layout -> rows (gq, gq+8), cols 2*tq, 2*tq+1 per n-tile
    const int r_lo = row_base + warp * 16 + gq;
    const int r_hi = r_lo + 8;
    #pragma unroll
    for (int nt = 0; nt < 8; nt++) {
        int c0 = nt * 8 + tq * 2;
        float bx = bias[c0], by = bias[c0 + 1];
        if (r_lo < N_NODES) {
            float2 v = make_float2(acc[nt][0] + bx, acc[nt][1] + by);
            *(float2*)&support[(size_t)r_lo * D_OUT + c0] = v;
        }
        if (r_hi < N_NODES) {
            float2 v = make_float2(acc[nt][2] + bx, acc[nt][3] + by);
            *(float2*)&support[(size_t)r_hi * D_OUT + c0] = v;
        }
    }
}

// ---------------------------------------------------------------------------
// Kernel 2: build CSR rowptr from sorted edge_dst
//   rowptr[n] = first edge index with dst >= n ; rowptr[N_NODES] = N_EDGES
// ---------------------------------------------------------------------------
__global__ void rowptr_kernel(const int* __restrict__ edge_dst, int* __restrict__ rowptr) {
    int e = blockIdx.x * blockDim.x + threadIdx.x;
    if (e >= N_EDGES) return;
    int d = __ldg(&edge_dst[e]);
    if (e == 0) {
        for (int n = 0; n <= d; n++) rowptr[n] = 0;
    } else {
        int dp = __ldg(&edge_dst[e - 1]);
        for (int n = dp + 1; n <= d; n++) rowptr[n] = e;
    }
    if (e == N_EDGES - 1) {
        for (int n = d + 1; n <= N_NODES; n++) rowptr[n] = N_EDGES;
    }
}

// ---------------------------------------------------------------------------
// Kernel 3: node-centric aggregation + LeakyReLU, no atomics, direct store.
//   One warp per destination node; lane owns columns {lane, lane+32}.
// ---------------------------------------------------------------------------
__global__ __launch_bounds__(256) void agg_node_kernel(
    const int*   __restrict__ edge_src,
    const float* __restrict__ edge_val,
    const int*   __restrict__ rowptr,
    const float* __restrict__ support,
    float*       __restrict__ out)
{
    const int node = (blockIdx.x * blockDim.x + threadIdx.x) >> 5;
    const int lane = threadIdx.x & 31;
    if (node >= N_NODES) return;

    const int beg = __ldg(&rowptr[node]);
    const int end = __ldg(&rowptr[node + 1]);

    float acc0 = 0.f, acc1 = 0.f;
    #pragma unroll 4
    for (int e = beg; e < end; e++) {
        const int   s = __ldg(&edge_src[e]);   // warp-uniform broadcast
        const float v = __ldg(&edge_val[e]);
        const float* srow = &support[(size_t)s * D_OUT];
        acc0 += v * __ldg(&srow[lane]);
        acc1 += v * __ldg(&srow[lane + 32]);
    }
    acc0 = (acc0 >= 0.f) ? acc0 : NEG_SLOPE * acc0;
    acc1 = (acc1 >= 0.f) ? acc1 : NEG_SLOPE * acc1;
    out[(size_t)node * D_OUT + lane]      = acc0;
    out[(size_t)node * D_OUT + lane + 32] = acc1;
}

// ---------------------------------------------------------------------------
// Launch
// ---------------------------------------------------------------------------
extern "C" void kernel_launch(void* const* d_in, const int* in_sizes, int n_in,
                              void* d_out, int out_size) {
    const float* x        = (const float*)d_in[0];
    const float* W        = (const float*)d_in[1];
    const float* b        = (const float*)d_in[2];
    const int*   edge_src = (const int*)  d_in[3];
    const int*   edge_dst = (const int*)  d_in[4];
    const float* edge_val = (const float*)d_in[5];
    float* out = (float*)d_out;

    float* support;
    cudaGetSymbolAddress((void**)&support, g_support);
    int* rowptr;
    cudaGetSymbolAddress((void**)&rowptr, g_rowptr);

    // 1. CSR rowptr from sorted edge_dst
    rowptr_kernel<<<(N_EDGES + 255) / 256, 256>>>(edge_dst, rowptr);

    // 2. tf32 tensor-core projection
    gemm_tf32_kernel<<<(N_NODES + 127) / 128, 256>>>(x, W, b, support);

    // 3. fused aggregation + LeakyReLU (warp per node)
    const int n_warps  = N_NODES;
    const int n_blocks = (n_warps * 32 + 255) / 256;
    agg_node_kernel<<<n_blocks, 256>>>(edge_src, edge_val, rowptr, support, out);
}